// round 6
// baseline (speedup 1.0000x reference)
#include <cuda_runtime.h>
#include <cuda_fp16.h>
#include <math.h>
#include <stdint.h>

#define N_NODES 20000
#define F_DIM   256
#define HID     128
#define OUTC    7
#define E_EDGES 320000
#define SB      157      // stats blocks, 128 rows each
#define BKT     64       // neighbor bucket capacity per node

// ---------------- scratch ----------------
__device__ float   g_stat[SB][2][F_DIM];
__device__ float   g_mean[F_DIM];
__device__ float   g_rstd[F_DIM];
__device__ int     g_deg[N_NODES];
__device__ float   g_dinv[N_NODES];
__device__ int     g_cur[N_NODES];
__device__ int     g_csrc[N_NODES * BKT];        // bucketed in-neighbors
__device__ float   g_c0p[64][2][HID];
__device__ float   g_c0[HID];
__device__ __half2 g_g1h[(size_t)N_NODES * 64];  // UNSCALED linear1 output (+c0), fp16
__device__ float   g_g2[N_NODES * 8];            // UNSCALED linear2 output

__device__ __forceinline__ uint32_t f2tf(float f) {
    uint32_t r; asm("cvt.rna.tf32.f32 %0, %1;" : "=r"(r) : "f"(f)); return r;
}
__device__ __forceinline__ void mma8(float* c, uint32_t a0, uint32_t a1, uint32_t a2,
                                     uint32_t a3, uint32_t b0, uint32_t b1) {
    asm volatile(
        "mma.sync.aligned.m16n8k8.row.col.f32.tf32.tf32.f32 "
        "{%0,%1,%2,%3},{%4,%5,%6,%7},{%8,%9},{%0,%1,%2,%3};"
        : "+f"(c[0]), "+f"(c[1]), "+f"(c[2]), "+f"(c[3])
        : "r"(a0), "r"(a1), "r"(a2), "r"(a3), "r"(b0), "r"(b1));
}

// ============ K_A: stats partials (157) | deg/cur init (79) | c0 partials (64) ============
__global__ void __launch_bounds__(256) kA(const float* __restrict__ x,
                                          const float* __restrict__ emb,
                                          const float* __restrict__ W1) {
    int b = blockIdx.x, t = threadIdx.x;
    if (b < SB) {
        int r0 = b * 128;
        float s = 0.f, q = 0.f;
        for (int r = 0; r < 128; ++r) {
            int rr = r0 + r;
            if (rr < N_NODES) {
                float v = x[(size_t)rr * F_DIM + t];
                s += v; q += v * v;
            }
        }
        g_stat[b][0][t] = s;
        g_stat[b][1][t] = q;
    } else if (b < SB + 79) {
        int i = (b - SB) * 256 + t;
        if (i < N_NODES) { g_deg[i] = 1; g_cur[i] = 0; }
    } else {
        __shared__ float se[252];
        int cb = b - SB - 79;
        int f0 = cb * 4;
        for (int i = t; i < 252; i += 256) se[i] = emb[f0 * 63 + i];
        __syncthreads();
        int h = t & 127, fp = t >> 7;
        float acc = 0.f;
        #pragma unroll
        for (int q2 = 0; q2 < 2; ++q2) {
            int f = f0 + fp * 2 + q2;
            const float* wrow = W1 + (size_t)f * 64 * HID + h;
            const float* ee = se + (fp * 2 + q2) * 63;
            #pragma unroll 7
            for (int j = 0; j < 63; ++j) acc += ee[j] * wrow[(size_t)j * HID];
        }
        g_c0p[cb][fp][h] = acc;
    }
}

// ============ K_B: finalize stats+c0 (1) | degree count (157) | bucket scatter (313) ============
__global__ void __launch_bounds__(256) kB(const int* __restrict__ ei) {
    int b = blockIdx.x, t = threadIdx.x;
    if (b == 0) {
        float s = 0.f, q = 0.f;
        for (int i = 0; i < SB; ++i) { s += g_stat[i][0][t]; q += g_stat[i][1][t]; }
        float m = s / N_NODES;
        float var = fmaxf(q / N_NODES - m * m, 0.f);
        float sd = sqrtf(var);
        if (sd == 0.f) sd = 1.f;
        g_mean[t] = m; g_rstd[t] = 1.f / sd;
        if (t < HID) {
            float c = 0.f;
            for (int i = 0; i < 64; ++i) c += g_c0p[i][0][t] + g_c0p[i][1][t];
            g_c0[t] = c;
        }
    } else if (b <= SB) {
        int base = ((b - 1) * 256 + t) * 8;
        if (base < E_EDGES) {
            const int4* p = (const int4*)(ei + E_EDGES + base);
            int4 d0 = p[0], d1 = p[1];
            atomicAdd(&g_deg[d0.x], 1); atomicAdd(&g_deg[d0.y], 1);
            atomicAdd(&g_deg[d0.z], 1); atomicAdd(&g_deg[d0.w], 1);
            atomicAdd(&g_deg[d1.x], 1); atomicAdd(&g_deg[d1.y], 1);
            atomicAdd(&g_deg[d1.z], 1); atomicAdd(&g_deg[d1.w], 1);
        }
    } else {
        int base = ((b - SB - 1) * 256 + t) * 4;
        if (base < E_EDGES) {
            int4 s4 = *(const int4*)(ei + base);
            int4 d4 = *(const int4*)(ei + E_EDGES + base);
            int s[4] = {s4.x, s4.y, s4.z, s4.w};
            int d[4] = {d4.x, d4.y, d4.z, d4.w};
            int p[4];
            #pragma unroll
            for (int i = 0; i < 4; ++i) p[i] = atomicAdd(&g_cur[d[i]], 1);
            #pragma unroll
            for (int i = 0; i < 4; ++i)
                if (p[i] < BKT) g_csrc[d[i] * BKT + p[i]] = s[i];
        }
    }
}

// ============ K_C: dinv (block 0) | tf32 tensor-core gemm1 (313), fp16 epilogue ============
__global__ void __launch_bounds__(256) kC(const float* __restrict__ x,
                                          const float* __restrict__ W1) {
    __shared__ uint32_t sxh[64 * 36];
    __shared__ uint32_t sxl[64 * 36];
    __shared__ uint32_t swh[32 * 136];
    int t = threadIdx.x;
    if (blockIdx.x == 0) {
        for (int i = t; i < N_NODES; i += 256)
            g_dinv[i] = rsqrtf((float)g_deg[i]);
        return;
    }
    int r0 = (blockIdx.x - 1) * 64;
    int w = t >> 5, l = t & 31;
    int mw = w & 1, nw = w >> 1;
    int g = l >> 2, tg = l & 3;
    float c[2][4][4];
    #pragma unroll
    for (int i = 0; i < 2; ++i)
        #pragma unroll
        for (int j = 0; j < 4; ++j)
            #pragma unroll
            for (int k = 0; k < 4; ++k) c[i][j][k] = 0.f;

    for (int kc = 0; kc < 8; ++kc) {
        int k0 = kc * 32;
        #pragma unroll
        for (int i = 0; i < 8; ++i) {                   // x tile 64x32, standardized
            int e = t + i * 256;
            int row = e >> 5, col = e & 31;
            int rr = min(r0 + row, N_NODES - 1);
            int cc = k0 + col;
            float v = (x[(size_t)rr * F_DIM + cc] - g_mean[cc]) * g_rstd[cc];
            uint32_t hi = f2tf(v);
            float lo = v - __uint_as_float(hi);
            sxh[row * 36 + col] = hi;
            sxl[row * 36 + col] = f2tf(lo);
        }
        #pragma unroll
        for (int i = 0; i < 16; ++i) {                  // W tile 32x128
            int e = t + i * 256;
            int n = e & 127, kk = e >> 7;
            swh[kk * 136 + n] = f2tf(W1[((size_t)(k0 + kk) * 64 + 63) * HID + n]);
        }
        __syncthreads();
        #pragma unroll
        for (int ks = 0; ks < 4; ++ks) {
            int kb = ks * 8;
            uint32_t ah[2][4], al[2][4];
            #pragma unroll
            for (int mt = 0; mt < 2; ++mt) {
                int mr = mw * 32 + mt * 16 + g;
                ah[mt][0] = sxh[mr * 36 + kb + tg];        al[mt][0] = sxl[mr * 36 + kb + tg];
                ah[mt][1] = sxh[(mr + 8) * 36 + kb + tg];  al[mt][1] = sxl[(mr + 8) * 36 + kb + tg];
                ah[mt][2] = sxh[mr * 36 + kb + tg + 4];    al[mt][2] = sxl[mr * 36 + kb + tg + 4];
                ah[mt][3] = sxh[(mr + 8) * 36 + kb + tg + 4]; al[mt][3] = sxl[(mr + 8) * 36 + kb + tg + 4];
            }
            #pragma unroll
            for (int nt = 0; nt < 4; ++nt) {
                int nc = nw * 32 + nt * 8 + g;
                uint32_t b0 = swh[(kb + tg) * 136 + nc];
                uint32_t b1 = swh[(kb + tg + 4) * 136 + nc];
                #pragma unroll
                for (int mt = 0; mt < 2; ++mt) {
                    mma8(c[mt][nt], ah[mt][0], ah[mt][1], ah[mt][2], ah[mt][3], b0, b1);
                    mma8(c[mt][nt], al[mt][0], al[mt][1], al[mt][2], al[mt][3], b0, b1);
                }
            }
        }
        __syncthreads();
    }
    #pragma unroll
    for (int mt = 0; mt < 2; ++mt) {
        int row0 = r0 + mw * 32 + mt * 16 + g;
        #pragma unroll
        for (int nt = 0; nt < 4; ++nt) {
            int col = nw * 32 + nt * 8 + 2 * tg;
            float cc0 = g_c0[col], cc1 = g_c0[col + 1];
            if (row0 < N_NODES)
                g_g1h[(size_t)row0 * 64 + (col >> 1)] =
                    __floats2half2_rn(c[mt][nt][0] + cc0, c[mt][nt][1] + cc1);
            if (row0 + 8 < N_NODES)
                g_g1h[(size_t)(row0 + 8) * 64 + (col >> 1)] =
                    __floats2half2_rn(c[mt][nt][2] + cc0, c[mt][nt][3] + cc1);
        }
    }
}

__device__ __forceinline__ void accum_h4(float4& acc, uint2 u, float ds) {
    __half2 p0 = *(__half2*)&u.x, p1 = *(__half2*)&u.y;
    float2 f0 = __half22float2(p0), f1 = __half22float2(p1);
    acc.x += f0.x * ds; acc.y += f0.y * ds;
    acc.z += f1.x * ds; acc.w += f1.y * ds;
}

// ============ K_E: conv1 aggregate + relu + gemm2, fused (one warp per node) ============
__global__ void __launch_bounds__(256) kE(const float* __restrict__ b1,
                                          const float* __restrict__ W2) {
    int t = threadIdx.x, w = t >> 5, l = t & 31;
    int n = blockIdx.x * 8 + w;                 // 2500 blocks x 8 warps
    float w2r[4][7];
    #pragma unroll
    for (int j = 0; j < 4; ++j)
        #pragma unroll
        for (int o = 0; o < 7; ++o) w2r[j][o] = W2[(4 * l + j) * OUTC + o];
    float4 b1v = ((const float4*)b1)[l];

    float dn = g_dinv[n];
    float4 acc = make_float4(0.f, 0.f, 0.f, 0.f);
    {
        uint2 u = *(const uint2*)(g_g1h + (size_t)n * 64 + 2 * l);
        accum_h4(acc, u, dn);
    }
    const int* bkt = g_csrc + n * BKT;
    int ne = min(g_deg[n] - 1, BKT);
    int e = 0;
    for (; e + 3 < ne; e += 4) {
        int s0 = bkt[e], s1 = bkt[e + 1], s2 = bkt[e + 2], s3 = bkt[e + 3];
        float d0 = g_dinv[s0], d1 = g_dinv[s1], d2 = g_dinv[s2], d3 = g_dinv[s3];
        uint2 u0 = *(const uint2*)(g_g1h + (size_t)s0 * 64 + 2 * l);
        uint2 u1 = *(const uint2*)(g_g1h + (size_t)s1 * 64 + 2 * l);
        uint2 u2 = *(const uint2*)(g_g1h + (size_t)s2 * 64 + 2 * l);
        uint2 u3 = *(const uint2*)(g_g1h + (size_t)s3 * 64 + 2 * l);
        accum_h4(acc, u0, d0); accum_h4(acc, u1, d1);
        accum_h4(acc, u2, d2); accum_h4(acc, u3, d3);
    }
    for (; e < ne; ++e) {
        int s0 = bkt[e];
        float d0 = g_dinv[s0];
        uint2 u0 = *(const uint2*)(g_g1h + (size_t)s0 * 64 + 2 * l);
        accum_h4(acc, u0, d0);
    }
    float h0 = fmaxf(acc.x * dn + b1v.x, 0.f);
    float h1 = fmaxf(acc.y * dn + b1v.y, 0.f);
    float h2 = fmaxf(acc.z * dn + b1v.z, 0.f);
    float h3 = fmaxf(acc.w * dn + b1v.w, 0.f);
    float po[7];
    #pragma unroll
    for (int o = 0; o < 7; ++o)
        po[o] = h0 * w2r[0][o] + h1 * w2r[1][o] + h2 * w2r[2][o] + h3 * w2r[3][o];
    #pragma unroll
    for (int o = 0; o < 7; ++o)
        #pragma unroll
        for (int d2 = 16; d2 > 0; d2 >>= 1)
            po[o] += __shfl_xor_sync(0xffffffffu, po[o], d2);
    if (l == 0) {
        float4* gp = (float4*)(g_g2 + n * 8);
        gp[0] = make_float4(po[0], po[1], po[2], po[3]);
        gp[1] = make_float4(po[4], po[5], po[6], 0.f);
    }
}

// ============ K_F: conv2 aggregate + bias + log_softmax ============
__global__ void __launch_bounds__(128) kF(const float* __restrict__ b2,
                                          float* __restrict__ out) {
    int t = threadIdx.x;
    int n = blockIdx.x * 16 + (t >> 3);
    int o = t & 7;
    float dn = g_dinv[n];
    float acc = g_g2[n * 8 + o] * dn;
    const int* bkt = g_csrc + n * BKT;
    int ne = min(g_deg[n] - 1, BKT);
    int e = 0;
    for (; e + 3 < ne; e += 4) {
        int s0 = bkt[e], s1 = bkt[e + 1], s2 = bkt[e + 2], s3 = bkt[e + 3];
        float v0 = g_g2[s0 * 8 + o] * g_dinv[s0];
        float v1 = g_g2[s1 * 8 + o] * g_dinv[s1];
        float v2 = g_g2[s2 * 8 + o] * g_dinv[s2];
        float v3 = g_g2[s3 * 8 + o] * g_dinv[s3];
        acc += (v0 + v1) + (v2 + v3);
    }
    for (; e < ne; ++e) {
        int s0 = bkt[e];
        acc += g_g2[s0 * 8 + o] * g_dinv[s0];
    }
    float v = (o < OUTC) ? (acc * dn + b2[o]) : -3.0e38f;
    float m = v;
    #pragma unroll
    for (int d = 1; d < 8; d <<= 1) m = fmaxf(m, __shfl_xor_sync(0xffffffffu, m, d));
    float ex = (o < OUTC) ? expf(v - m) : 0.f;
    float s2 = ex;
    #pragma unroll
    for (int d = 1; d < 8; d <<= 1) s2 += __shfl_xor_sync(0xffffffffu, s2, d);
    if (o < OUTC) out[n * OUTC + o] = v - m - logf(s2);
}

// ---------------- launcher ----------------
extern "C" void kernel_launch(void* const* d_in, const int* in_sizes, int n_in,
                              void* d_out, int out_size) {
    const float* x   = (const float*)d_in[0];
    const float* emb = (const float*)d_in[1];
    const float* W1  = (const float*)d_in[2];
    const float* b1  = (const float*)d_in[3];
    const float* W2  = (const float*)d_in[4];
    const float* b2  = (const float*)d_in[5];
    const int*   ei  = (const int*)d_in[6];
    float* out = (float*)d_out;

    kA<<<300, 256>>>(x, emb, W1);        // stats partials | deg/cur init | c0 partials
    kB<<<1 + SB + 313, 256>>>(ei);       // stats+c0 finalize | count | bucket scatter
    kC<<<314, 256>>>(x, W1);             // dinv | tf32 gemm1 (fp16 out)
    kE<<<2500, 256>>>(b1, W2);           // agg1 + relu + gemm2 fused (warp/node)
    kF<<<1250, 128>>>(b2, out);          // agg2 + log_softmax
}

// round 7
// speedup vs baseline: 1.4124x; 1.4124x over previous
#include <cuda_runtime.h>
#include <math.h>
#include <stdint.h>

#define N_NODES 20000
#define F_DIM   256
#define HID     128
#define OUTC    7
#define E_EDGES 320000
#define SB      157      // stats blocks, 128 rows each
#define BKT     64       // neighbor bucket capacity per node

// ---------------- scratch ----------------
__device__ float g_stat[SB][2][F_DIM];
__device__ float g_mean[F_DIM];
__device__ float g_rstd[F_DIM];
__device__ int   g_deg[N_NODES];
__device__ float g_dinv[N_NODES];
__device__ int   g_cur[N_NODES];
__device__ int   g_csrc[N_NODES * BKT];         // bucketed in-neighbors
__device__ float g_c0p[64][2][HID];
__device__ float g_c0[HID];
__device__ float g_g1[(size_t)N_NODES * HID];   // UNSCALED linear1 output (+c0)
__device__ float g_g2[N_NODES * 8];             // UNSCALED linear2 output

__device__ __forceinline__ uint32_t f2tf(float f) {
    uint32_t r; asm("cvt.rna.tf32.f32 %0, %1;" : "=r"(r) : "f"(f)); return r;
}
__device__ __forceinline__ void mma8(float* c, uint32_t a0, uint32_t a1, uint32_t a2,
                                     uint32_t a3, uint32_t b0, uint32_t b1) {
    asm volatile(
        "mma.sync.aligned.m16n8k8.row.col.f32.tf32.tf32.f32 "
        "{%0,%1,%2,%3},{%4,%5,%6,%7},{%8,%9},{%0,%1,%2,%3};"
        : "+f"(c[0]), "+f"(c[1]), "+f"(c[2]), "+f"(c[3])
        : "r"(a0), "r"(a1), "r"(a2), "r"(a3), "r"(b0), "r"(b1));
}

// ============ K_A: stats partials (157) | deg/cur init (79) | c0 partials (64) ============
__global__ void __launch_bounds__(256) kA(const float* __restrict__ x,
                                          const float* __restrict__ emb,
                                          const float* __restrict__ W1) {
    int b = blockIdx.x, t = threadIdx.x;
    if (b < SB) {
        int r0 = b * 128;
        float s = 0.f, q = 0.f;
        for (int r = 0; r < 128; ++r) {
            int rr = r0 + r;
            if (rr < N_NODES) {
                float v = x[(size_t)rr * F_DIM + t];
                s += v; q += v * v;
            }
        }
        g_stat[b][0][t] = s;
        g_stat[b][1][t] = q;
    } else if (b < SB + 79) {
        int i = (b - SB) * 256 + t;
        if (i < N_NODES) { g_deg[i] = 1; g_cur[i] = 0; }
    } else {
        __shared__ float se[252];
        int cb = b - SB - 79;
        int f0 = cb * 4;
        for (int i = t; i < 252; i += 256) se[i] = emb[f0 * 63 + i];
        __syncthreads();
        int h = t & 127, fp = t >> 7;
        float acc = 0.f;
        #pragma unroll
        for (int q2 = 0; q2 < 2; ++q2) {
            int f = f0 + fp * 2 + q2;
            const float* wrow = W1 + (size_t)f * 64 * HID + h;
            const float* ee = se + (fp * 2 + q2) * 63;
            #pragma unroll 7
            for (int j = 0; j < 63; ++j) acc += ee[j] * wrow[(size_t)j * HID];
        }
        g_c0p[cb][fp][h] = acc;
    }
}

// ============ K_B: finalize stats+c0 (1) | degree count (157) | bucket scatter (313) ============
__global__ void __launch_bounds__(256) kB(const int* __restrict__ ei) {
    int b = blockIdx.x, t = threadIdx.x;
    if (b == 0) {
        float s = 0.f, q = 0.f;
        for (int i = 0; i < SB; ++i) { s += g_stat[i][0][t]; q += g_stat[i][1][t]; }
        float m = s / N_NODES;
        float var = fmaxf(q / N_NODES - m * m, 0.f);
        float sd = sqrtf(var);
        if (sd == 0.f) sd = 1.f;
        g_mean[t] = m; g_rstd[t] = 1.f / sd;
        if (t < HID) {
            float c = 0.f;
            for (int i = 0; i < 64; ++i) c += g_c0p[i][0][t] + g_c0p[i][1][t];
            g_c0[t] = c;
        }
    } else if (b <= SB) {
        int base = ((b - 1) * 256 + t) * 8;
        if (base < E_EDGES) {
            const int4* p = (const int4*)(ei + E_EDGES + base);
            int4 d0 = p[0], d1 = p[1];
            atomicAdd(&g_deg[d0.x], 1); atomicAdd(&g_deg[d0.y], 1);
            atomicAdd(&g_deg[d0.z], 1); atomicAdd(&g_deg[d0.w], 1);
            atomicAdd(&g_deg[d1.x], 1); atomicAdd(&g_deg[d1.y], 1);
            atomicAdd(&g_deg[d1.z], 1); atomicAdd(&g_deg[d1.w], 1);
        }
    } else {
        int base = ((b - SB - 1) * 256 + t) * 4;
        if (base < E_EDGES) {
            int4 s4 = *(const int4*)(ei + base);
            int4 d4 = *(const int4*)(ei + E_EDGES + base);
            int s[4] = {s4.x, s4.y, s4.z, s4.w};
            int d[4] = {d4.x, d4.y, d4.z, d4.w};
            int p[4];
            #pragma unroll
            for (int i = 0; i < 4; ++i) p[i] = atomicAdd(&g_cur[d[i]], 1);
            #pragma unroll
            for (int i = 0; i < 4; ++i)
                if (p[i] < BKT) g_csrc[d[i] * BKT + p[i]] = s[i];
        }
    }
}

// ============ K_C: dinv (block 0) | tf32 tensor-core gemm1 (313) ============
__global__ void __launch_bounds__(256) kC(const float* __restrict__ x,
                                          const float* __restrict__ W1) {
    __shared__ uint32_t sxh[64 * 36];
    __shared__ uint32_t sxl[64 * 36];
    __shared__ uint32_t swh[32 * 136];
    int t = threadIdx.x;
    if (blockIdx.x == 0) {
        for (int i = t; i < N_NODES; i += 256)
            g_dinv[i] = rsqrtf((float)g_deg[i]);
        return;
    }
    int r0 = (blockIdx.x - 1) * 64;
    int w = t >> 5, l = t & 31;
    int mw = w & 1, nw = w >> 1;
    int g = l >> 2, tg = l & 3;
    float c[2][4][4];
    #pragma unroll
    for (int i = 0; i < 2; ++i)
        #pragma unroll
        for (int j = 0; j < 4; ++j)
            #pragma unroll
            for (int k = 0; k < 4; ++k) c[i][j][k] = 0.f;

    for (int kc = 0; kc < 8; ++kc) {
        int k0 = kc * 32;
        #pragma unroll
        for (int i = 0; i < 8; ++i) {                   // x tile 64x32, standardized
            int e = t + i * 256;
            int row = e >> 5, col = e & 31;
            int rr = min(r0 + row, N_NODES - 1);
            int cc = k0 + col;
            float v = (x[(size_t)rr * F_DIM + cc] - g_mean[cc]) * g_rstd[cc];
            uint32_t hi = f2tf(v);
            float lo = v - __uint_as_float(hi);
            sxh[row * 36 + col] = hi;
            sxl[row * 36 + col] = f2tf(lo);
        }
        #pragma unroll
        for (int i = 0; i < 16; ++i) {                  // W tile 32x128
            int e = t + i * 256;
            int n = e & 127, kk = e >> 7;
            swh[kk * 136 + n] = f2tf(W1[((size_t)(k0 + kk) * 64 + 63) * HID + n]);
        }
        __syncthreads();
        #pragma unroll
        for (int ks = 0; ks < 4; ++ks) {
            int kb = ks * 8;
            uint32_t ah[2][4], al[2][4];
            #pragma unroll
            for (int mt = 0; mt < 2; ++mt) {
                int mr = mw * 32 + mt * 16 + g;
                ah[mt][0] = sxh[mr * 36 + kb + tg];        al[mt][0] = sxl[mr * 36 + kb + tg];
                ah[mt][1] = sxh[(mr + 8) * 36 + kb + tg];  al[mt][1] = sxl[(mr + 8) * 36 + kb + tg];
                ah[mt][2] = sxh[mr * 36 + kb + tg + 4];    al[mt][2] = sxl[mr * 36 + kb + tg + 4];
                ah[mt][3] = sxh[(mr + 8) * 36 + kb + tg + 4]; al[mt][3] = sxl[(mr + 8) * 36 + kb + tg + 4];
            }
            #pragma unroll
            for (int nt = 0; nt < 4; ++nt) {
                int nc = nw * 32 + nt * 8 + g;
                uint32_t b0 = swh[(kb + tg) * 136 + nc];
                uint32_t b1 = swh[(kb + tg + 4) * 136 + nc];
                #pragma unroll
                for (int mt = 0; mt < 2; ++mt) {
                    mma8(c[mt][nt], ah[mt][0], ah[mt][1], ah[mt][2], ah[mt][3], b0, b1);
                    mma8(c[mt][nt], al[mt][0], al[mt][1], al[mt][2], al[mt][3], b0, b1);
                }
            }
        }
        __syncthreads();
    }
    #pragma unroll
    for (int mt = 0; mt < 2; ++mt) {
        int row0 = r0 + mw * 32 + mt * 16 + g;
        #pragma unroll
        for (int nt = 0; nt < 4; ++nt) {
            int col = nw * 32 + nt * 8 + 2 * tg;
            float cc0 = g_c0[col], cc1 = g_c0[col + 1];
            if (row0 < N_NODES) {
                float2 v; v.x = c[mt][nt][0] + cc0; v.y = c[mt][nt][1] + cc1;
                *(float2*)&g_g1[(size_t)row0 * HID + col] = v;
            }
            if (row0 + 8 < N_NODES) {
                float2 v; v.x = c[mt][nt][2] + cc0; v.y = c[mt][nt][3] + cc1;
                *(float2*)&g_g1[(size_t)(row0 + 8) * HID + col] = v;
            }
        }
    }
}

// ============ K_E: conv1 aggregate + relu + gemm2, fused (one warp per node) ============
// Indices + dinv prefetched by lanes, broadcast via shfl -> neighbor loop is
// pure independent float4 gathers (max MLP).
__global__ void __launch_bounds__(256) kE(const float* __restrict__ b1,
                                          const float* __restrict__ W2) {
    int t = threadIdx.x, w = t >> 5, l = t & 31;
    int n = blockIdx.x * 8 + w;                 // 2500 blocks x 8 warps
    float w2r[4][7];
    #pragma unroll
    for (int j = 0; j < 4; ++j)
        #pragma unroll
        for (int o = 0; o < 7; ++o) w2r[j][o] = W2[(4 * l + j) * OUTC + o];
    float4 b1v = ((const float4*)b1)[l];

    float dn = g_dinv[n];
    const int* bkt = g_csrc + n * BKT;
    int ne = min(g_deg[n] - 1, BKT);

    // lane-parallel prefetch of indices + their dinv
    int myidx = (l < ne) ? bkt[l] : 0;
    float mydv = (l < ne) ? g_dinv[myidx] : 0.f;

    float4 a = ((const float4*)(g_g1 + (size_t)n * HID))[l];
    float4 acc;
    acc.x = a.x * dn; acc.y = a.y * dn; acc.z = a.z * dn; acc.w = a.w * dn;

    int nel = min(ne, 32);
    #pragma unroll 4
    for (int e = 0; e < nel; ++e) {
        int   s  = __shfl_sync(0xffffffffu, myidx, e);
        float ds = __shfl_sync(0xffffffffu, mydv, e);
        float4 v = ((const float4*)(g_g1 + (size_t)s * HID))[l];
        acc.x += v.x * ds; acc.y += v.y * ds; acc.z += v.z * ds; acc.w += v.w * ds;
    }
    for (int e = 32; e < ne; ++e) {             // rare tail (deg > 33)
        int s = bkt[e];
        float ds = g_dinv[s];
        float4 v = ((const float4*)(g_g1 + (size_t)s * HID))[l];
        acc.x += v.x * ds; acc.y += v.y * ds; acc.z += v.z * ds; acc.w += v.w * ds;
    }

    float h0 = fmaxf(acc.x * dn + b1v.x, 0.f);
    float h1 = fmaxf(acc.y * dn + b1v.y, 0.f);
    float h2 = fmaxf(acc.z * dn + b1v.z, 0.f);
    float h3 = fmaxf(acc.w * dn + b1v.w, 0.f);
    float po[7];
    #pragma unroll
    for (int o = 0; o < 7; ++o)
        po[o] = h0 * w2r[0][o] + h1 * w2r[1][o] + h2 * w2r[2][o] + h3 * w2r[3][o];
    #pragma unroll
    for (int o = 0; o < 7; ++o)
        #pragma unroll
        for (int d2 = 16; d2 > 0; d2 >>= 1)
            po[o] += __shfl_xor_sync(0xffffffffu, po[o], d2);
    if (l == 0) {
        float4* gp = (float4*)(g_g2 + n * 8);
        gp[0] = make_float4(po[0], po[1], po[2], po[3]);
        gp[1] = make_float4(po[4], po[5], po[6], 0.f);
    }
}

// ============ K_F: conv2 aggregate + bias + log_softmax ============
__global__ void __launch_bounds__(128) kF(const float* __restrict__ b2,
                                          float* __restrict__ out) {
    int t = threadIdx.x;
    int n = blockIdx.x * 16 + (t >> 3);
    int o = t & 7;
    float dn = g_dinv[n];
    float acc = g_g2[n * 8 + o] * dn;
    const int* bkt = g_csrc + n * BKT;
    int ne = min(g_deg[n] - 1, BKT);
    int e = 0;
    for (; e + 3 < ne; e += 4) {
        int s0 = bkt[e], s1 = bkt[e + 1], s2 = bkt[e + 2], s3 = bkt[e + 3];
        float v0 = g_g2[s0 * 8 + o] * g_dinv[s0];
        float v1 = g_g2[s1 * 8 + o] * g_dinv[s1];
        float v2 = g_g2[s2 * 8 + o] * g_dinv[s2];
        float v3 = g_g2[s3 * 8 + o] * g_dinv[s3];
        acc += (v0 + v1) + (v2 + v3);
    }
    for (; e < ne; ++e) {
        int s0 = bkt[e];
        acc += g_g2[s0 * 8 + o] * g_dinv[s0];
    }
    float v = (o < OUTC) ? (acc * dn + b2[o]) : -3.0e38f;
    float m = v;
    #pragma unroll
    for (int d = 1; d < 8; d <<= 1) m = fmaxf(m, __shfl_xor_sync(0xffffffffu, m, d));
    float ex = (o < OUTC) ? expf(v - m) : 0.f;
    float s2 = ex;
    #pragma unroll
    for (int d = 1; d < 8; d <<= 1) s2 += __shfl_xor_sync(0xffffffffu, s2, d);
    if (o < OUTC) out[n * OUTC + o] = v - m - logf(s2);
}

// ---------------- launcher ----------------
extern "C" void kernel_launch(void* const* d_in, const int* in_sizes, int n_in,
                              void* d_out, int out_size) {
    const float* x   = (const float*)d_in[0];
    const float* emb = (const float*)d_in[1];
    const float* W1  = (const float*)d_in[2];
    const float* b1  = (const float*)d_in[3];
    const float* W2  = (const float*)d_in[4];
    const float* b2  = (const float*)d_in[5];
    const int*   ei  = (const int*)d_in[6];
    float* out = (float*)d_out;

    kA<<<300, 256>>>(x, emb, W1);        // stats partials | deg/cur init | c0 partials
    kB<<<1 + SB + 313, 256>>>(ei);       // stats+c0 finalize | count | bucket scatter
    kC<<<314, 256>>>(x, W1);             // dinv | tf32 gemm1
    kE<<<2500, 256>>>(b1, W2);           // agg1 + relu + gemm2 fused (warp/node)
    kF<<<1250, 128>>>(b2, out);          // agg2 + log_softmax
}

// round 8
// speedup vs baseline: 1.5255x; 1.0800x over previous
#include <cuda_runtime.h>
#include <math.h>
#include <stdint.h>

#define N_NODES 20000
#define F_DIM   256
#define HID     128
#define OUTC    7
#define E_EDGES 320000
#define SB      157      // stats blocks, 128 rows each
#define BKT     64       // neighbor bucket capacity per node

// ---------------- scratch ----------------
__device__ float g_stat[SB][2][F_DIM];
__device__ float g_mean[F_DIM];
__device__ float g_rstd[F_DIM];
__device__ int   g_deg[N_NODES];
__device__ float g_dinv[N_NODES];
__device__ int   g_cur[N_NODES];
__device__ int   g_csrc[N_NODES * BKT];         // bucketed in-neighbors
__device__ float g_c0p[64][2][HID];
__device__ float g_c0[HID];
__device__ float g_g1[(size_t)N_NODES * HID];   // UNSCALED linear1 output (+c0)
__device__ float g_g2[N_NODES * 8];             // UNSCALED linear2 output

__device__ __forceinline__ uint32_t f2tf(float f) {
    uint32_t r; asm("cvt.rna.tf32.f32 %0, %1;" : "=r"(r) : "f"(f)); return r;
}
__device__ __forceinline__ void mma8(float* c, uint32_t a0, uint32_t a1, uint32_t a2,
                                     uint32_t a3, uint32_t b0, uint32_t b1) {
    asm volatile(
        "mma.sync.aligned.m16n8k8.row.col.f32.tf32.tf32.f32 "
        "{%0,%1,%2,%3},{%4,%5,%6,%7},{%8,%9},{%0,%1,%2,%3};"
        : "+f"(c[0]), "+f"(c[1]), "+f"(c[2]), "+f"(c[3])
        : "r"(a0), "r"(a1), "r"(a2), "r"(a3), "r"(b0), "r"(b1));
}

// ============ K_A: stats partials (157) | deg/cur init (79) | c0 partials (64) ============
__global__ void __launch_bounds__(256) kA(const float* __restrict__ x,
                                          const float* __restrict__ emb,
                                          const float* __restrict__ W1) {
    int b = blockIdx.x, t = threadIdx.x;
    if (b < SB) {
        int r0 = b * 128;
        float s = 0.f, q = 0.f;
        for (int r = 0; r < 128; ++r) {
            int rr = r0 + r;
            if (rr < N_NODES) {
                float v = x[(size_t)rr * F_DIM + t];
                s += v; q += v * v;
            }
        }
        g_stat[b][0][t] = s;
        g_stat[b][1][t] = q;
    } else if (b < SB + 79) {
        int i = (b - SB) * 256 + t;
        if (i < N_NODES) { g_deg[i] = 1; g_cur[i] = 0; }
    } else {
        __shared__ float se[252];
        int cb = b - SB - 79;
        int f0 = cb * 4;
        for (int i = t; i < 252; i += 256) se[i] = emb[f0 * 63 + i];
        __syncthreads();
        int h = t & 127, fp = t >> 7;
        float acc = 0.f;
        #pragma unroll
        for (int q2 = 0; q2 < 2; ++q2) {
            int f = f0 + fp * 2 + q2;
            const float* wrow = W1 + (size_t)f * 64 * HID + h;
            const float* ee = se + (fp * 2 + q2) * 63;
            #pragma unroll 7
            for (int j = 0; j < 63; ++j) acc += ee[j] * wrow[(size_t)j * HID];
        }
        g_c0p[cb][fp][h] = acc;
    }
}

// ============ K_B: finalize stats+c0 (1) | degree count (157) | bucket scatter (313) ============
__global__ void __launch_bounds__(256) kB(const int* __restrict__ ei) {
    int b = blockIdx.x, t = threadIdx.x;
    if (b == 0) {
        float s = 0.f, q = 0.f;
        for (int i = 0; i < SB; ++i) { s += g_stat[i][0][t]; q += g_stat[i][1][t]; }
        float m = s / N_NODES;
        float var = fmaxf(q / N_NODES - m * m, 0.f);
        float sd = sqrtf(var);
        if (sd == 0.f) sd = 1.f;
        g_mean[t] = m; g_rstd[t] = 1.f / sd;
        if (t < HID) {
            float c = 0.f;
            for (int i = 0; i < 64; ++i) c += g_c0p[i][0][t] + g_c0p[i][1][t];
            g_c0[t] = c;
        }
    } else if (b <= SB) {
        int base = ((b - 1) * 256 + t) * 8;
        if (base < E_EDGES) {
            const int4* p = (const int4*)(ei + E_EDGES + base);
            int4 d0 = p[0], d1 = p[1];
            atomicAdd(&g_deg[d0.x], 1); atomicAdd(&g_deg[d0.y], 1);
            atomicAdd(&g_deg[d0.z], 1); atomicAdd(&g_deg[d0.w], 1);
            atomicAdd(&g_deg[d1.x], 1); atomicAdd(&g_deg[d1.y], 1);
            atomicAdd(&g_deg[d1.z], 1); atomicAdd(&g_deg[d1.w], 1);
        }
    } else {
        int base = ((b - SB - 1) * 256 + t) * 4;
        if (base < E_EDGES) {
            int4 s4 = *(const int4*)(ei + base);
            int4 d4 = *(const int4*)(ei + E_EDGES + base);
            int s[4] = {s4.x, s4.y, s4.z, s4.w};
            int d[4] = {d4.x, d4.y, d4.z, d4.w};
            int p[4];
            #pragma unroll
            for (int i = 0; i < 4; ++i) p[i] = atomicAdd(&g_cur[d[i]], 1);
            #pragma unroll
            for (int i = 0; i < 4; ++i)
                if (p[i] < BKT) g_csrc[d[i] * BKT + p[i]] = s[i];
        }
    }
}

// ============ K_C: dinv (block 0) | tf32 tensor-core gemm1 (313) ============
__global__ void __launch_bounds__(256) kC(const float* __restrict__ x,
                                          const float* __restrict__ W1) {
    __shared__ uint32_t sxh[64 * 36];
    __shared__ uint32_t sxl[64 * 36];
    __shared__ uint32_t swh[32 * 136];
    int t = threadIdx.x;
    if (blockIdx.x == 0) {
        for (int i = t; i < N_NODES; i += 256)
            g_dinv[i] = rsqrtf((float)g_deg[i]);
        return;
    }
    int r0 = (blockIdx.x - 1) * 64;
    int w = t >> 5, l = t & 31;
    int mw = w & 1, nw = w >> 1;
    int g = l >> 2, tg = l & 3;
    float c[2][4][4];
    #pragma unroll
    for (int i = 0; i < 2; ++i)
        #pragma unroll
        for (int j = 0; j < 4; ++j)
            #pragma unroll
            for (int k = 0; k < 4; ++k) c[i][j][k] = 0.f;

    for (int kc = 0; kc < 8; ++kc) {
        int k0 = kc * 32;
        #pragma unroll
        for (int i = 0; i < 8; ++i) {                   // x tile 64x32, standardized
            int e = t + i * 256;
            int row = e >> 5, col = e & 31;
            int rr = min(r0 + row, N_NODES - 1);
            int cc = k0 + col;
            float v = (x[(size_t)rr * F_DIM + cc] - g_mean[cc]) * g_rstd[cc];
            uint32_t hi = f2tf(v);
            float lo = v - __uint_as_float(hi);
            sxh[row * 36 + col] = hi;
            sxl[row * 36 + col] = f2tf(lo);
        }
        #pragma unroll
        for (int i = 0; i < 16; ++i) {                  // W tile 32x128
            int e = t + i * 256;
            int n = e & 127, kk = e >> 7;
            swh[kk * 136 + n] = f2tf(W1[((size_t)(k0 + kk) * 64 + 63) * HID + n]);
        }
        __syncthreads();
        #pragma unroll
        for (int ks = 0; ks < 4; ++ks) {
            int kb = ks * 8;
            uint32_t ah[2][4], al[2][4];
            #pragma unroll
            for (int mt = 0; mt < 2; ++mt) {
                int mr = mw * 32 + mt * 16 + g;
                ah[mt][0] = sxh[mr * 36 + kb + tg];        al[mt][0] = sxl[mr * 36 + kb + tg];
                ah[mt][1] = sxh[(mr + 8) * 36 + kb + tg];  al[mt][1] = sxl[(mr + 8) * 36 + kb + tg];
                ah[mt][2] = sxh[mr * 36 + kb + tg + 4];    al[mt][2] = sxl[mr * 36 + kb + tg + 4];
                ah[mt][3] = sxh[(mr + 8) * 36 + kb + tg + 4]; al[mt][3] = sxl[(mr + 8) * 36 + kb + tg + 4];
            }
            #pragma unroll
            for (int nt = 0; nt < 4; ++nt) {
                int nc = nw * 32 + nt * 8 + g;
                uint32_t b0 = swh[(kb + tg) * 136 + nc];
                uint32_t b1 = swh[(kb + tg + 4) * 136 + nc];
                #pragma unroll
                for (int mt = 0; mt < 2; ++mt) {
                    mma8(c[mt][nt], ah[mt][0], ah[mt][1], ah[mt][2], ah[mt][3], b0, b1);
                    mma8(c[mt][nt], al[mt][0], al[mt][1], al[mt][2], al[mt][3], b0, b1);
                }
            }
        }
        __syncthreads();
    }
    #pragma unroll
    for (int mt = 0; mt < 2; ++mt) {
        int row0 = r0 + mw * 32 + mt * 16 + g;
        #pragma unroll
        for (int nt = 0; nt < 4; ++nt) {
            int col = nw * 32 + nt * 8 + 2 * tg;
            float cc0 = g_c0[col], cc1 = g_c0[col + 1];
            if (row0 < N_NODES) {
                float2 v; v.x = c[mt][nt][0] + cc0; v.y = c[mt][nt][1] + cc1;
                *(float2*)&g_g1[(size_t)row0 * HID + col] = v;
            }
            if (row0 + 8 < N_NODES) {
                float2 v; v.x = c[mt][nt][2] + cc0; v.y = c[mt][nt][3] + cc1;
                *(float2*)&g_g1[(size_t)(row0 + 8) * HID + col] = v;
            }
        }
    }
}

// ============ K_E: conv1 aggregate + relu + gemm2, fused (one warp per node) ============
// W2 in smem (frees ~28 regs -> higher occupancy); indices+dinv prefetched by
// lanes and broadcast via shfl -> neighbor loop is pure independent float4 gathers.
__global__ void __launch_bounds__(256, 5) kE(const float* __restrict__ b1,
                                             const float* __restrict__ W2) {
    __shared__ float sW2[HID * OUTC];           // [h][o], 3.5 KB
    int t = threadIdx.x, w = t >> 5, l = t & 31;
    for (int i = t; i < HID * OUTC; i += 256) sW2[i] = W2[i];
    __syncthreads();

    int n = blockIdx.x * 8 + w;                 // 2500 blocks x 8 warps
    float4 b1v = ((const float4*)b1)[l];

    float dn = g_dinv[n];
    const int* bkt = g_csrc + n * BKT;
    int ne = min(g_deg[n] - 1, BKT);

    // lane-parallel prefetch of indices + their dinv
    int myidx = (l < ne) ? bkt[l] : 0;
    float mydv = (l < ne) ? g_dinv[myidx] : 0.f;

    float4 a = ((const float4*)(g_g1 + (size_t)n * HID))[l];
    float4 acc;
    acc.x = a.x * dn; acc.y = a.y * dn; acc.z = a.z * dn; acc.w = a.w * dn;

    int nel = min(ne, 32);
    #pragma unroll 8
    for (int e = 0; e < nel; ++e) {
        int   s  = __shfl_sync(0xffffffffu, myidx, e);
        float ds = __shfl_sync(0xffffffffu, mydv, e);
        float4 v = ((const float4*)(g_g1 + (size_t)s * HID))[l];
        acc.x += v.x * ds; acc.y += v.y * ds; acc.z += v.z * ds; acc.w += v.w * ds;
    }
    for (int e = 32; e < ne; ++e) {             // rare tail (deg > 33)
        int s = bkt[e];
        float ds = g_dinv[s];
        float4 v = ((const float4*)(g_g1 + (size_t)s * HID))[l];
        acc.x += v.x * ds; acc.y += v.y * ds; acc.z += v.z * ds; acc.w += v.w * ds;
    }

    float h0 = fmaxf(acc.x * dn + b1v.x, 0.f);
    float h1 = fmaxf(acc.y * dn + b1v.y, 0.f);
    float h2 = fmaxf(acc.z * dn + b1v.z, 0.f);
    float h3 = fmaxf(acc.w * dn + b1v.w, 0.f);
    const float* w0 = sW2 + (4 * l + 0) * OUTC;
    const float* w1 = sW2 + (4 * l + 1) * OUTC;
    const float* w2 = sW2 + (4 * l + 2) * OUTC;
    const float* w3 = sW2 + (4 * l + 3) * OUTC;
    float po[7];
    #pragma unroll
    for (int o = 0; o < 7; ++o)
        po[o] = h0 * w0[o] + h1 * w1[o] + h2 * w2[o] + h3 * w3[o];
    #pragma unroll
    for (int o = 0; o < 7; ++o)
        #pragma unroll
        for (int d2 = 16; d2 > 0; d2 >>= 1)
            po[o] += __shfl_xor_sync(0xffffffffu, po[o], d2);
    if (l == 0) {
        float4* gp = (float4*)(g_g2 + n * 8);
        gp[0] = make_float4(po[0], po[1], po[2], po[3]);
        gp[1] = make_float4(po[4], po[5], po[6], 0.f);
    }
}

// ============ K_F: conv2 aggregate + bias + log_softmax ============
__global__ void __launch_bounds__(128) kF(const float* __restrict__ b2,
                                          float* __restrict__ out) {
    int t = threadIdx.x;
    int n = blockIdx.x * 16 + (t >> 3);
    int o = t & 7;
    float dn = g_dinv[n];
    float acc = g_g2[n * 8 + o] * dn;
    const int* bkt = g_csrc + n * BKT;
    int ne = min(g_deg[n] - 1, BKT);
    int e = 0;
    for (; e + 3 < ne; e += 4) {
        int s0 = bkt[e], s1 = bkt[e + 1], s2 = bkt[e + 2], s3 = bkt[e + 3];
        float v0 = g_g2[s0 * 8 + o] * g_dinv[s0];
        float v1 = g_g2[s1 * 8 + o] * g_dinv[s1];
        float v2 = g_g2[s2 * 8 + o] * g_dinv[s2];
        float v3 = g_g2[s3 * 8 + o] * g_dinv[s3];
        acc += (v0 + v1) + (v2 + v3);
    }
    for (; e < ne; ++e) {
        int s0 = bkt[e];
        acc += g_g2[s0 * 8 + o] * g_dinv[s0];
    }
    float v = (o < OUTC) ? (acc * dn + b2[o]) : -3.0e38f;
    float m = v;
    #pragma unroll
    for (int d = 1; d < 8; d <<= 1) m = fmaxf(m, __shfl_xor_sync(0xffffffffu, m, d));
    float ex = (o < OUTC) ? expf(v - m) : 0.f;
    float s2 = ex;
    #pragma unroll
    for (int d = 1; d < 8; d <<= 1) s2 += __shfl_xor_sync(0xffffffffu, s2, d);
    if (o < OUTC) out[n * OUTC + o] = v - m - logf(s2);
}

// ---------------- launcher ----------------
extern "C" void kernel_launch(void* const* d_in, const int* in_sizes, int n_in,
                              void* d_out, int out_size) {
    const float* x   = (const float*)d_in[0];
    const float* emb = (const float*)d_in[1];
    const float* W1  = (const float*)d_in[2];
    const float* b1  = (const float*)d_in[3];
    const float* W2  = (const float*)d_in[4];
    const float* b2  = (const float*)d_in[5];
    const int*   ei  = (const int*)d_in[6];
    float* out = (float*)d_out;

    kA<<<300, 256>>>(x, emb, W1);        // stats partials | deg/cur init | c0 partials
    kB<<<1 + SB + 313, 256>>>(ei);       // stats+c0 finalize | count | bucket scatter
    kC<<<314, 256>>>(x, W1);             // dinv | tf32 gemm1
    kE<<<2500, 256>>>(b1, W2);           // agg1 + relu + gemm2 fused (warp/node)
    kF<<<1250, 128>>>(b2, out);          // agg2 + log_softmax
}

// round 9
// speedup vs baseline: 1.6364x; 1.0727x over previous
#include <cuda_runtime.h>
#include <math.h>
#include <stdint.h>

#define N_NODES 20000
#define F_DIM   256
#define HID     128
#define OUTC    7
#define E_EDGES 320000
#define SB      157      // stats blocks, 128 rows each
#define BKT     64       // neighbor bucket capacity per node

// ---------------- scratch ----------------
__device__ float g_stat[SB][2][F_DIM];
__device__ float g_mean[F_DIM];
__device__ float g_rstd[F_DIM];
__device__ int   g_deg[N_NODES];
__device__ float g_dinv[N_NODES];
__device__ int   g_cur[N_NODES];
__device__ int   g_csrc[N_NODES * BKT];         // bucketed in-neighbors
__device__ float g_c0p[64][2][HID];
__device__ float g_c0[HID];
__device__ float g_g1[(size_t)N_NODES * HID];   // linear1 output (+c0), PRE-SCALED by dinv[row]
__device__ float g_g2[N_NODES * 8];             // linear2 output, PRE-SCALED by dinv[row]

__device__ __forceinline__ uint32_t f2tf(float f) {
    uint32_t r; asm("cvt.rna.tf32.f32 %0, %1;" : "=r"(r) : "f"(f)); return r;
}
__device__ __forceinline__ void mma8(float* c, uint32_t a0, uint32_t a1, uint32_t a2,
                                     uint32_t a3, uint32_t b0, uint32_t b1) {
    asm volatile(
        "mma.sync.aligned.m16n8k8.row.col.f32.tf32.tf32.f32 "
        "{%0,%1,%2,%3},{%4,%5,%6,%7},{%8,%9},{%0,%1,%2,%3};"
        : "+f"(c[0]), "+f"(c[1]), "+f"(c[2]), "+f"(c[3])
        : "r"(a0), "r"(a1), "r"(a2), "r"(a3), "r"(b0), "r"(b1));
}

// ============ K_A: stats partials (157) | deg/cur init (79) | c0 partials (64) ============
__global__ void __launch_bounds__(256) kA(const float* __restrict__ x,
                                          const float* __restrict__ emb,
                                          const float* __restrict__ W1) {
    int b = blockIdx.x, t = threadIdx.x;
    if (b < SB) {
        int r0 = b * 128;
        float s = 0.f, q = 0.f;
        for (int r = 0; r < 128; ++r) {
            int rr = r0 + r;
            if (rr < N_NODES) {
                float v = x[(size_t)rr * F_DIM + t];
                s += v; q += v * v;
            }
        }
        g_stat[b][0][t] = s;
        g_stat[b][1][t] = q;
    } else if (b < SB + 79) {
        int i = (b - SB) * 256 + t;
        if (i < N_NODES) { g_deg[i] = 1; g_cur[i] = 0; }
    } else {
        __shared__ float se[252];
        int cb = b - SB - 79;
        int f0 = cb * 4;
        for (int i = t; i < 252; i += 256) se[i] = emb[f0 * 63 + i];
        __syncthreads();
        int h = t & 127, fp = t >> 7;
        float acc = 0.f;
        #pragma unroll
        for (int q2 = 0; q2 < 2; ++q2) {
            int f = f0 + fp * 2 + q2;
            const float* wrow = W1 + (size_t)f * 64 * HID + h;
            const float* ee = se + (fp * 2 + q2) * 63;
            #pragma unroll 7
            for (int j = 0; j < 63; ++j) acc += ee[j] * wrow[(size_t)j * HID];
        }
        g_c0p[cb][fp][h] = acc;
    }
}

// ============ K_B: finalize stats+c0 (1) | degree count (157) | bucket scatter (313) ============
__global__ void __launch_bounds__(256) kB(const int* __restrict__ ei) {
    int b = blockIdx.x, t = threadIdx.x;
    if (b == 0) {
        float s = 0.f, q = 0.f;
        for (int i = 0; i < SB; ++i) { s += g_stat[i][0][t]; q += g_stat[i][1][t]; }
        float m = s / N_NODES;
        float var = fmaxf(q / N_NODES - m * m, 0.f);
        float sd = sqrtf(var);
        if (sd == 0.f) sd = 1.f;
        g_mean[t] = m; g_rstd[t] = 1.f / sd;
        if (t < HID) {
            float c = 0.f;
            for (int i = 0; i < 64; ++i) c += g_c0p[i][0][t] + g_c0p[i][1][t];
            g_c0[t] = c;
        }
    } else if (b <= SB) {
        int base = ((b - 1) * 256 + t) * 8;
        if (base < E_EDGES) {
            const int4* p = (const int4*)(ei + E_EDGES + base);
            int4 d0 = p[0], d1 = p[1];
            atomicAdd(&g_deg[d0.x], 1); atomicAdd(&g_deg[d0.y], 1);
            atomicAdd(&g_deg[d0.z], 1); atomicAdd(&g_deg[d0.w], 1);
            atomicAdd(&g_deg[d1.x], 1); atomicAdd(&g_deg[d1.y], 1);
            atomicAdd(&g_deg[d1.z], 1); atomicAdd(&g_deg[d1.w], 1);
        }
    } else {
        int base = ((b - SB - 1) * 256 + t) * 4;
        if (base < E_EDGES) {
            int4 s4 = *(const int4*)(ei + base);
            int4 d4 = *(const int4*)(ei + E_EDGES + base);
            int s[4] = {s4.x, s4.y, s4.z, s4.w};
            int d[4] = {d4.x, d4.y, d4.z, d4.w};
            int p[4];
            #pragma unroll
            for (int i = 0; i < 4; ++i) p[i] = atomicAdd(&g_cur[d[i]], 1);
            #pragma unroll
            for (int i = 0; i < 4; ++i)
                if (p[i] < BKT) g_csrc[d[i] * BKT + p[i]] = s[i];
        }
    }
}

// ============ K_C: dinv (block 0) | tf32 tensor-core gemm1 (313), dinv-scaled epilogue ============
__global__ void __launch_bounds__(256) kC(const float* __restrict__ x,
                                          const float* __restrict__ W1) {
    __shared__ uint32_t sxh[64 * 36];
    __shared__ uint32_t sxl[64 * 36];
    __shared__ uint32_t swh[32 * 136];
    int t = threadIdx.x;
    if (blockIdx.x == 0) {
        for (int i = t; i < N_NODES; i += 256)
            g_dinv[i] = rsqrtf((float)g_deg[i]);
        return;
    }
    int r0 = (blockIdx.x - 1) * 64;
    int w = t >> 5, l = t & 31;
    int mw = w & 1, nw = w >> 1;
    int g = l >> 2, tg = l & 3;
    float c[2][4][4];
    #pragma unroll
    for (int i = 0; i < 2; ++i)
        #pragma unroll
        for (int j = 0; j < 4; ++j)
            #pragma unroll
            for (int k = 0; k < 4; ++k) c[i][j][k] = 0.f;

    for (int kc = 0; kc < 8; ++kc) {
        int k0 = kc * 32;
        #pragma unroll
        for (int i = 0; i < 8; ++i) {                   // x tile 64x32, standardized
            int e = t + i * 256;
            int row = e >> 5, col = e & 31;
            int rr = min(r0 + row, N_NODES - 1);
            int cc = k0 + col;
            float v = (x[(size_t)rr * F_DIM + cc] - g_mean[cc]) * g_rstd[cc];
            uint32_t hi = f2tf(v);
            float lo = v - __uint_as_float(hi);
            sxh[row * 36 + col] = hi;
            sxl[row * 36 + col] = f2tf(lo);
        }
        #pragma unroll
        for (int i = 0; i < 16; ++i) {                  // W tile 32x128
            int e = t + i * 256;
            int n = e & 127, kk = e >> 7;
            swh[kk * 136 + n] = f2tf(W1[((size_t)(k0 + kk) * 64 + 63) * HID + n]);
        }
        __syncthreads();
        #pragma unroll
        for (int ks = 0; ks < 4; ++ks) {
            int kb = ks * 8;
            uint32_t ah[2][4], al[2][4];
            #pragma unroll
            for (int mt = 0; mt < 2; ++mt) {
                int mr = mw * 32 + mt * 16 + g;
                ah[mt][0] = sxh[mr * 36 + kb + tg];        al[mt][0] = sxl[mr * 36 + kb + tg];
                ah[mt][1] = sxh[(mr + 8) * 36 + kb + tg];  al[mt][1] = sxl[(mr + 8) * 36 + kb + tg];
                ah[mt][2] = sxh[mr * 36 + kb + tg + 4];    al[mt][2] = sxl[mr * 36 + kb + tg + 4];
                ah[mt][3] = sxh[(mr + 8) * 36 + kb + tg + 4]; al[mt][3] = sxl[(mr + 8) * 36 + kb + tg + 4];
            }
            #pragma unroll
            for (int nt = 0; nt < 4; ++nt) {
                int nc = nw * 32 + nt * 8 + g;
                uint32_t b0 = swh[(kb + tg) * 136 + nc];
                uint32_t b1 = swh[(kb + tg + 4) * 136 + nc];
                #pragma unroll
                for (int mt = 0; mt < 2; ++mt) {
                    mma8(c[mt][nt], ah[mt][0], ah[mt][1], ah[mt][2], ah[mt][3], b0, b1);
                    mma8(c[mt][nt], al[mt][0], al[mt][1], al[mt][2], al[mt][3], b0, b1);
                }
            }
        }
        __syncthreads();
    }
    #pragma unroll
    for (int mt = 0; mt < 2; ++mt) {
        int row0 = r0 + mw * 32 + mt * 16 + g;
        float dv0 = (row0 < N_NODES) ? rsqrtf((float)g_deg[row0]) : 0.f;
        float dv1 = (row0 + 8 < N_NODES) ? rsqrtf((float)g_deg[row0 + 8]) : 0.f;
        #pragma unroll
        for (int nt = 0; nt < 4; ++nt) {
            int col = nw * 32 + nt * 8 + 2 * tg;
            float cc0 = g_c0[col], cc1 = g_c0[col + 1];
            if (row0 < N_NODES) {
                float2 v; v.x = (c[mt][nt][0] + cc0) * dv0; v.y = (c[mt][nt][1] + cc1) * dv0;
                *(float2*)&g_g1[(size_t)row0 * HID + col] = v;
            }
            if (row0 + 8 < N_NODES) {
                float2 v; v.x = (c[mt][nt][2] + cc0) * dv1; v.y = (c[mt][nt][3] + cc1) * dv1;
                *(float2*)&g_g1[(size_t)(row0 + 8) * HID + col] = v;
            }
        }
    }
}

// ============ K_E: conv1 aggregate + relu + gemm2, fused (one warp per node) ============
// g1 pre-scaled by dinv[src] -> gather loop is pure loads; W2 in smem.
__global__ void __launch_bounds__(256, 6) kE(const float* __restrict__ b1,
                                             const float* __restrict__ W2) {
    __shared__ float sW2[HID * OUTC];           // [h][o], 3.5 KB
    int t = threadIdx.x, w = t >> 5, l = t & 31;
    for (int i = t; i < HID * OUTC; i += 256) sW2[i] = W2[i];
    __syncthreads();

    int n = blockIdx.x * 8 + w;                 // 2500 blocks x 8 warps
    float4 b1v = ((const float4*)b1)[l];

    float dn = g_dinv[n];
    const int* bkt = g_csrc + n * BKT;
    int ne = min(g_deg[n] - 1, BKT);

    // lane-parallel prefetch of indices
    int myidx = (l < ne) ? bkt[l] : 0;

    float4 acc = ((const float4*)(g_g1 + (size_t)n * HID))[l];  // self (pre-scaled)

    int nel = min(ne, 32);
    #pragma unroll 8
    for (int e = 0; e < nel; ++e) {
        int s = __shfl_sync(0xffffffffu, myidx, e);
        float4 v = ((const float4*)(g_g1 + (size_t)s * HID))[l];
        acc.x += v.x; acc.y += v.y; acc.z += v.z; acc.w += v.w;
    }
    for (int e = 32; e < ne; ++e) {             // rare tail (deg > 33)
        int s = bkt[e];
        float4 v = ((const float4*)(g_g1 + (size_t)s * HID))[l];
        acc.x += v.x; acc.y += v.y; acc.z += v.z; acc.w += v.w;
    }

    float h0 = fmaxf(acc.x * dn + b1v.x, 0.f);
    float h1 = fmaxf(acc.y * dn + b1v.y, 0.f);
    float h2 = fmaxf(acc.z * dn + b1v.z, 0.f);
    float h3 = fmaxf(acc.w * dn + b1v.w, 0.f);
    const float* w0 = sW2 + (4 * l + 0) * OUTC;
    const float* w1 = sW2 + (4 * l + 1) * OUTC;
    const float* w2 = sW2 + (4 * l + 2) * OUTC;
    const float* w3 = sW2 + (4 * l + 3) * OUTC;
    float po[7];
    #pragma unroll
    for (int o = 0; o < 7; ++o)
        po[o] = h0 * w0[o] + h1 * w1[o] + h2 * w2[o] + h3 * w3[o];
    #pragma unroll
    for (int o = 0; o < 7; ++o)
        #pragma unroll
        for (int d2 = 16; d2 > 0; d2 >>= 1)
            po[o] += __shfl_xor_sync(0xffffffffu, po[o], d2);
    if (l == 0) {
        float4* gp = (float4*)(g_g2 + n * 8);
        gp[0] = make_float4(po[0] * dn, po[1] * dn, po[2] * dn, po[3] * dn);
        gp[1] = make_float4(po[4] * dn, po[5] * dn, po[6] * dn, 0.f);
    }
}

// ============ K_F: conv2 aggregate + bias + log_softmax ============
// g2 pre-scaled by dinv[src] -> pure gather.
__global__ void __launch_bounds__(128) kF(const float* __restrict__ b2,
                                          float* __restrict__ out) {
    int t = threadIdx.x;
    int n = blockIdx.x * 16 + (t >> 3);
    int o = t & 7;
    float dn = g_dinv[n];
    float acc = g_g2[n * 8 + o];                // self (pre-scaled)
    const int* bkt = g_csrc + n * BKT;
    int ne = min(g_deg[n] - 1, BKT);
    int e = 0;
    for (; e + 3 < ne; e += 4) {
        int s0 = bkt[e], s1 = bkt[e + 1], s2 = bkt[e + 2], s3 = bkt[e + 3];
        float v0 = g_g2[s0 * 8 + o];
        float v1 = g_g2[s1 * 8 + o];
        float v2 = g_g2[s2 * 8 + o];
        float v3 = g_g2[s3 * 8 + o];
        acc += (v0 + v1) + (v2 + v3);
    }
    for (; e < ne; ++e)
        acc += g_g2[bkt[e] * 8 + o];
    float v = (o < OUTC) ? (acc * dn + b2[o]) : -3.0e38f;
    float m = v;
    #pragma unroll
    for (int d = 1; d < 8; d <<= 1) m = fmaxf(m, __shfl_xor_sync(0xffffffffu, m, d));
    float ex = (o < OUTC) ? expf(v - m) : 0.f;
    float s2 = ex;
    #pragma unroll
    for (int d = 1; d < 8; d <<= 1) s2 += __shfl_xor_sync(0xffffffffu, s2, d);
    if (o < OUTC) out[n * OUTC + o] = v - m - logf(s2);
}

// ---------------- launcher ----------------
extern "C" void kernel_launch(void* const* d_in, const int* in_sizes, int n_in,
                              void* d_out, int out_size) {
    const float* x   = (const float*)d_in[0];
    const float* emb = (const float*)d_in[1];
    const float* W1  = (const float*)d_in[2];
    const float* b1  = (const float*)d_in[3];
    const float* W2  = (const float*)d_in[4];
    const float* b2  = (const float*)d_in[5];
    const int*   ei  = (const int*)d_in[6];
    float* out = (float*)d_out;

    kA<<<300, 256>>>(x, emb, W1);        // stats partials | deg/cur init | c0 partials
    kB<<<1 + SB + 313, 256>>>(ei);       // stats+c0 finalize | count | bucket scatter
    kC<<<314, 256>>>(x, W1);             // dinv | tf32 gemm1 (dinv-scaled out)
    kE<<<2500, 256>>>(b1, W2);           // agg1 + relu + gemm2 fused (warp/node)
    kF<<<1250, 128>>>(b2, out);          // agg2 + log_softmax
}

// round 11
// speedup vs baseline: 1.7593x; 1.0751x over previous
#include <cuda_runtime.h>
#include <math.h>
#include <stdint.h>

#define N_NODES 20000
#define F_DIM   256
#define HID     128
#define OUTC    7
#define E_EDGES 320000
#define SB      157      // stats blocks, 128 rows each
#define BKT     64       // neighbor bucket capacity per node

// ---------------- scratch ----------------
__device__ float g_stat[SB][2][F_DIM];
__device__ float g_mean[F_DIM];
__device__ float g_rstd[F_DIM];
__device__ int   g_deg[N_NODES];
__device__ float g_dinv[N_NODES];
__device__ int   g_cur[N_NODES];
__device__ int   g_csrc[N_NODES * BKT];         // bucketed in-neighbors
__device__ float g_c0p[64][2][HID];
__device__ float g_c0[HID];
__device__ float g_g1[(size_t)N_NODES * HID];   // linear1 output (+c0), PRE-SCALED by dinv[row]
__device__ float g_g2[N_NODES * 8];             // linear2 output, PRE-SCALED by dinv[row]

__device__ __forceinline__ uint32_t f2tf(float f) {
    uint32_t r; asm("cvt.rna.tf32.f32 %0, %1;" : "=r"(r) : "f"(f)); return r;
}
__device__ __forceinline__ void mma8(float* c, uint32_t a0, uint32_t a1, uint32_t a2,
                                     uint32_t a3, uint32_t b0, uint32_t b1) {
    asm volatile(
        "mma.sync.aligned.m16n8k8.row.col.f32.tf32.tf32.f32 "
        "{%0,%1,%2,%3},{%4,%5,%6,%7},{%8,%9},{%0,%1,%2,%3};"
        : "+f"(c[0]), "+f"(c[1]), "+f"(c[2]), "+f"(c[3])
        : "r"(a0), "r"(a1), "r"(a2), "r"(a3), "r"(b0), "r"(b1));
}

// ============ K_A: stats partials (157) | deg/cur init (79) | c0 partials (64) ============
__global__ void __launch_bounds__(256) kA(const float* __restrict__ x,
                                          const float* __restrict__ emb,
                                          const float* __restrict__ W1) {
    int b = blockIdx.x, t = threadIdx.x;
    if (b < SB) {
        int r0 = b * 128;
        float s = 0.f, q = 0.f;
        for (int r = 0; r < 128; ++r) {
            int rr = r0 + r;
            if (rr < N_NODES) {
                float v = x[(size_t)rr * F_DIM + t];
                s += v; q += v * v;
            }
        }
        g_stat[b][0][t] = s;
        g_stat[b][1][t] = q;
    } else if (b < SB + 79) {
        int i = (b - SB) * 256 + t;
        if (i < N_NODES) { g_deg[i] = 1; g_cur[i] = 0; }
    } else {
        __shared__ float se[252];
        int cb = b - SB - 79;
        int f0 = cb * 4;
        for (int i = t; i < 252; i += 256) se[i] = emb[f0 * 63 + i];
        __syncthreads();
        int h = t & 127, fp = t >> 7;
        float acc = 0.f;
        #pragma unroll
        for (int q2 = 0; q2 < 2; ++q2) {
            int f = f0 + fp * 2 + q2;
            const float* wrow = W1 + (size_t)f * 64 * HID + h;
            const float* ee = se + (fp * 2 + q2) * 63;
            #pragma unroll 7
            for (int j = 0; j < 63; ++j) acc += ee[j] * wrow[(size_t)j * HID];
        }
        g_c0p[cb][fp][h] = acc;
    }
}

// ============ K_B: finalize stats+c0 (1) | degree count (157) | bucket scatter (313) ============
__global__ void __launch_bounds__(256) kB(const int* __restrict__ ei) {
    int b = blockIdx.x, t = threadIdx.x;
    if (b == 0) {
        float s = 0.f, q = 0.f;
        for (int i = 0; i < SB; ++i) { s += g_stat[i][0][t]; q += g_stat[i][1][t]; }
        float m = s / N_NODES;
        float var = fmaxf(q / N_NODES - m * m, 0.f);
        float sd = sqrtf(var);
        if (sd == 0.f) sd = 1.f;
        g_mean[t] = m; g_rstd[t] = 1.f / sd;
        if (t < HID) {
            float c = 0.f;
            for (int i = 0; i < 64; ++i) c += g_c0p[i][0][t] + g_c0p[i][1][t];
            g_c0[t] = c;
        }
    } else if (b <= SB) {
        int base = ((b - 1) * 256 + t) * 8;
        if (base < E_EDGES) {
            const int4* p = (const int4*)(ei + E_EDGES + base);
            int4 d0 = p[0], d1 = p[1];
            atomicAdd(&g_deg[d0.x], 1); atomicAdd(&g_deg[d0.y], 1);
            atomicAdd(&g_deg[d0.z], 1); atomicAdd(&g_deg[d0.w], 1);
            atomicAdd(&g_deg[d1.x], 1); atomicAdd(&g_deg[d1.y], 1);
            atomicAdd(&g_deg[d1.z], 1); atomicAdd(&g_deg[d1.w], 1);
        }
    } else {
        int base = ((b - SB - 1) * 256 + t) * 4;
        if (base < E_EDGES) {
            int4 s4 = *(const int4*)(ei + base);
            int4 d4 = *(const int4*)(ei + E_EDGES + base);
            int s[4] = {s4.x, s4.y, s4.z, s4.w};
            int d[4] = {d4.x, d4.y, d4.z, d4.w};
            int p[4];
            #pragma unroll
            for (int i = 0; i < 4; ++i) p[i] = atomicAdd(&g_cur[d[i]], 1);
            #pragma unroll
            for (int i = 0; i < 4; ++i)
                if (p[i] < BKT) g_csrc[d[i] * BKT + p[i]] = s[i];
        }
    }
}

// ============ K_C: dinv (block 0) | tf32 gemm1, 128-row tiles, single-precision tf32 ============
__global__ void __launch_bounds__(256, 2) kC(const float* __restrict__ x,
                                             const float* __restrict__ W1) {
    __shared__ uint32_t sxh[128 * 36];          // 18.4 KB
    __shared__ uint32_t swh[32 * 136];          // 17.4 KB
    int t = threadIdx.x;
    if (blockIdx.x == 0) {
        for (int i = t; i < N_NODES; i += 256)
            g_dinv[i] = rsqrtf((float)g_deg[i]);
        return;
    }
    int r0 = (blockIdx.x - 1) * 128;
    int w = t >> 5, l = t & 31;
    int mw = w & 1, nw = w >> 1;                // 2 m-halves (64 rows), 4 n-quarters (32 cols)
    int g = l >> 2, tg = l & 3;
    float c[4][4][4];
    #pragma unroll
    for (int i = 0; i < 4; ++i)
        #pragma unroll
        for (int j = 0; j < 4; ++j)
            #pragma unroll
            for (int k = 0; k < 4; ++k) c[i][j][k] = 0.f;

    for (int kc = 0; kc < 8; ++kc) {
        int k0 = kc * 32;
        #pragma unroll
        for (int i = 0; i < 16; ++i) {          // x tile 128x32, standardized -> tf32
            int e = t + i * 256;
            int row = e >> 5, col = e & 31;
            int rr = min(r0 + row, N_NODES - 1);
            int cc = k0 + col;
            float v = (x[(size_t)rr * F_DIM + cc] - g_mean[cc]) * g_rstd[cc];
            sxh[row * 36 + col] = f2tf(v);
        }
        #pragma unroll
        for (int i = 0; i < 16; ++i) {          // W tile 32x128
            int e = t + i * 256;
            int n = e & 127, kk = e >> 7;
            swh[kk * 136 + n] = f2tf(W1[((size_t)(k0 + kk) * 64 + 63) * HID + n]);
        }
        __syncthreads();
        #pragma unroll
        for (int ks = 0; ks < 4; ++ks) {
            int kb = ks * 8;
            uint32_t ah[4][4];
            #pragma unroll
            for (int mt = 0; mt < 4; ++mt) {
                int mr = mw * 64 + mt * 16 + g;
                ah[mt][0] = sxh[mr * 36 + kb + tg];
                ah[mt][1] = sxh[(mr + 8) * 36 + kb + tg];
                ah[mt][2] = sxh[mr * 36 + kb + tg + 4];
                ah[mt][3] = sxh[(mr + 8) * 36 + kb + tg + 4];
            }
            #pragma unroll
            for (int nt = 0; nt < 4; ++nt) {
                int nc = nw * 32 + nt * 8 + g;
                uint32_t b0 = swh[(kb + tg) * 136 + nc];
                uint32_t b1 = swh[(kb + tg + 4) * 136 + nc];
                #pragma unroll
                for (int mt = 0; mt < 4; ++mt)
                    mma8(c[mt][nt], ah[mt][0], ah[mt][1], ah[mt][2], ah[mt][3], b0, b1);
            }
        }
        __syncthreads();
    }
    #pragma unroll
    for (int mt = 0; mt < 4; ++mt) {
        int row0 = r0 + mw * 64 + mt * 16 + g;
        float dv0 = (row0 < N_NODES) ? rsqrtf((float)g_deg[row0]) : 0.f;
        float dv1 = (row0 + 8 < N_NODES) ? rsqrtf((float)g_deg[row0 + 8]) : 0.f;
        #pragma unroll
        for (int nt = 0; nt < 4; ++nt) {
            int col = nw * 32 + nt * 8 + 2 * tg;
            float cc0 = g_c0[col], cc1 = g_c0[col + 1];
            if (row0 < N_NODES) {
                float2 v; v.x = (c[mt][nt][0] + cc0) * dv0; v.y = (c[mt][nt][1] + cc1) * dv0;
                *(float2*)&g_g1[(size_t)row0 * HID + col] = v;
            }
            if (row0 + 8 < N_NODES) {
                float2 v; v.x = (c[mt][nt][2] + cc0) * dv1; v.y = (c[mt][nt][3] + cc1) * dv1;
                *(float2*)&g_g1[(size_t)(row0 + 8) * HID + col] = v;
            }
        }
    }
}

// ============ K_E: conv1 aggregate + relu + gemm2, fused (one warp per node) ============
__global__ void __launch_bounds__(256, 6) kE(const float* __restrict__ b1,
                                             const float* __restrict__ W2) {
    __shared__ float sW2[HID * OUTC];           // [h][o], 3.5 KB
    int t = threadIdx.x, w = t >> 5, l = t & 31;
    for (int i = t; i < HID * OUTC; i += 256) sW2[i] = W2[i];
    __syncthreads();

    int n = blockIdx.x * 8 + w;                 // 2500 blocks x 8 warps
    float4 b1v = ((const float4*)b1)[l];

    float dn = g_dinv[n];
    const int* bkt = g_csrc + n * BKT;
    int ne = min(g_deg[n] - 1, BKT);

    int myidx = (l < ne) ? bkt[l] : 0;          // lane-parallel index prefetch

    float4 acc = ((const float4*)(g_g1 + (size_t)n * HID))[l];  // self (pre-scaled)

    int nel = min(ne, 32);
    #pragma unroll 8
    for (int e = 0; e < nel; ++e) {
        int s = __shfl_sync(0xffffffffu, myidx, e);
        float4 v = ((const float4*)(g_g1 + (size_t)s * HID))[l];
        acc.x += v.x; acc.y += v.y; acc.z += v.z; acc.w += v.w;
    }
    for (int e = 32; e < ne; ++e) {             // rare tail (deg > 33)
        int s = bkt[e];
        float4 v = ((const float4*)(g_g1 + (size_t)s * HID))[l];
        acc.x += v.x; acc.y += v.y; acc.z += v.z; acc.w += v.w;
    }

    float h0 = fmaxf(acc.x * dn + b1v.x, 0.f);
    float h1 = fmaxf(acc.y * dn + b1v.y, 0.f);
    float h2 = fmaxf(acc.z * dn + b1v.z, 0.f);
    float h3 = fmaxf(acc.w * dn + b1v.w, 0.f);
    const float* w0 = sW2 + (4 * l + 0) * OUTC;
    const float* w1 = sW2 + (4 * l + 1) * OUTC;
    const float* w2 = sW2 + (4 * l + 2) * OUTC;
    const float* w3 = sW2 + (4 * l + 3) * OUTC;
    float po[7];
    #pragma unroll
    for (int o = 0; o < 7; ++o)
        po[o] = h0 * w0[o] + h1 * w1[o] + h2 * w2[o] + h3 * w3[o];
    #pragma unroll
    for (int o = 0; o < 7; ++o)
        #pragma unroll
        for (int d2 = 16; d2 > 0; d2 >>= 1)
            po[o] += __shfl_xor_sync(0xffffffffu, po[o], d2);
    if (l == 0) {
        float4* gp = (float4*)(g_g2 + n * 8);
        gp[0] = make_float4(po[0] * dn, po[1] * dn, po[2] * dn, po[3] * dn);
        gp[1] = make_float4(po[4] * dn, po[5] * dn, po[6] * dn, 0.f);
    }
}

// ============ K_F: conv2 aggregate + bias + log_softmax (8-lane subgroup prefetch) ============
__global__ void __launch_bounds__(128) kF(const float* __restrict__ b2,
                                          float* __restrict__ out) {
    int t = threadIdx.x;
    int l = t & 31;
    int n = blockIdx.x * 16 + (t >> 3);
    int o = t & 7;
    unsigned gm = 0xFFu << (l & 24);            // this 8-lane group's mask
    float dn = g_dinv[n];
    const int* bkt = g_csrc + n * BKT;
    int ne = min(g_deg[n] - 1, BKT);

    int i0 = (o < ne)      ? bkt[o]      : 0;
    int i1 = (8 + o < ne)  ? bkt[8 + o]  : 0;
    int i2 = (16 + o < ne) ? bkt[16 + o] : 0;
    int i3 = (24 + o < ne) ? bkt[24 + o] : 0;

    float acc = g_g2[n * 8 + o];                // self (pre-scaled)
    int nel = min(ne, 32);
    int full = nel >> 3, rem = nel & 7;
    int pidx[4] = {i0, i1, i2, i3};
    #pragma unroll
    for (int p = 0; p < 4; ++p) {
        if (p < full) {
            #pragma unroll
            for (int k = 0; k < 8; ++k) {
                int s = __shfl_sync(gm, pidx[p], k, 8);
                acc += g_g2[s * 8 + o];
            }
        } else if (p == full) {
            for (int k = 0; k < rem; ++k) {
                int s = __shfl_sync(gm, pidx[p], k, 8);
                acc += g_g2[s * 8 + o];
            }
        }
    }
    for (int e = 32; e < ne; ++e)               // rare tail
        acc += g_g2[bkt[e] * 8 + o];

    float v = (o < OUTC) ? (acc * dn + b2[o]) : -3.0e38f;
    float m = v;
    #pragma unroll
    for (int d = 1; d < 8; d <<= 1) m = fmaxf(m, __shfl_xor_sync(0xffffffffu, m, d));
    float ex = (o < OUTC) ? expf(v - m) : 0.f;
    float s2 = ex;
    #pragma unroll
    for (int d = 1; d < 8; d <<= 1) s2 += __shfl_xor_sync(0xffffffffu, s2, d);
    if (o < OUTC) out[n * OUTC + o] = v - m - logf(s2);
}

// ---------------- launcher ----------------
extern "C" void kernel_launch(void* const* d_in, const int* in_sizes, int n_in,
                              void* d_out, int out_size) {
    const float* x   = (const float*)d_in[0];
    const float* emb = (const float*)d_in[1];
    const float* W1  = (const float*)d_in[2];
    const float* b1  = (const float*)d_in[3];
    const float* W2  = (const float*)d_in[4];
    const float* b2  = (const float*)d_in[5];
    const int*   ei  = (const int*)d_in[6];
    float* out = (float*)d_out;

    kA<<<300, 256>>>(x, emb, W1);        // stats partials | deg/cur init | c0 partials
    kB<<<1 + SB + 313, 256>>>(ei);       // stats+c0 finalize | count | bucket scatter
    kC<<<158, 256>>>(x, W1);             // dinv | tf32 gemm1 (128-row tiles)
    kE<<<2500, 256>>>(b1, W2);           // agg1 + relu + gemm2 fused (warp/node)
    kF<<<1250, 128>>>(b2, out);          // agg2 + log_softmax
}

// round 13
// speedup vs baseline: 1.7601x; 1.0004x over previous
#include <cuda_runtime.h>
#include <cuda_fp16.h>
#include <math.h>
#include <stdint.h>

#define N_NODES 20000
#define F_DIM   256
#define HID     128
#define OUTC    7
#define E_EDGES 320000
#define SB      157      // stats blocks, 128 rows each
#define BKT     64       // neighbor bucket capacity per node

// ---------------- scratch ----------------
__device__ float   g_stat[SB][2][F_DIM];
__device__ float   g_mean[F_DIM];
__device__ float   g_rstd[F_DIM];
__device__ int     g_deg[N_NODES];
__device__ float   g_dinv[N_NODES];
__device__ int     g_cur[N_NODES];
__device__ int     g_csrc[N_NODES * BKT];        // bucketed in-neighbors
__device__ float   g_c0p[64][2][HID];
__device__ float   g_c0[HID];
__device__ __half2 g_g1h[(size_t)N_NODES * 64];  // linear1 out (+c0), PRE-SCALED by dinv, fp16
__device__ float   g_g2[N_NODES * 8];            // linear2 out, PRE-SCALED by dinv

__device__ __forceinline__ uint32_t f2tf(float f) {
    uint32_t r; asm("cvt.rna.tf32.f32 %0, %1;" : "=r"(r) : "f"(f)); return r;
}
__device__ __forceinline__ void mma8(float* c, uint32_t a0, uint32_t a1, uint32_t a2,
                                     uint32_t a3, uint32_t b0, uint32_t b1) {
    asm volatile(
        "mma.sync.aligned.m16n8k8.row.col.f32.tf32.tf32.f32 "
        "{%0,%1,%2,%3},{%4,%5,%6,%7},{%8,%9},{%0,%1,%2,%3};"
        : "+f"(c[0]), "+f"(c[1]), "+f"(c[2]), "+f"(c[3])
        : "r"(a0), "r"(a1), "r"(a2), "r"(a3), "r"(b0), "r"(b1));
}

// ============ K_A: stats partials (157) | deg/cur init (79) | c0 partials (64) ============
__global__ void __launch_bounds__(256) kA(const float* __restrict__ x,
                                          const float* __restrict__ emb,
                                          const float* __restrict__ W1) {
    int b = blockIdx.x, t = threadIdx.x;
    if (b < SB) {
        int r0 = b * 128;
        float s = 0.f, q = 0.f;
        for (int r = 0; r < 128; ++r) {
            int rr = r0 + r;
            if (rr < N_NODES) {
                float v = x[(size_t)rr * F_DIM + t];
                s += v; q += v * v;
            }
        }
        g_stat[b][0][t] = s;
        g_stat[b][1][t] = q;
    } else if (b < SB + 79) {
        int i = (b - SB) * 256 + t;
        if (i < N_NODES) { g_deg[i] = 1; g_cur[i] = 0; }
    } else {
        __shared__ float se[252];
        int cb = b - SB - 79;
        int f0 = cb * 4;
        for (int i = t; i < 252; i += 256) se[i] = emb[f0 * 63 + i];
        __syncthreads();
        int h = t & 127, fp = t >> 7;
        float acc = 0.f;
        #pragma unroll
        for (int q2 = 0; q2 < 2; ++q2) {
            int f = f0 + fp * 2 + q2;
            const float* wrow = W1 + (size_t)f * 64 * HID + h;
            const float* ee = se + (fp * 2 + q2) * 63;
            #pragma unroll 7
            for (int j = 0; j < 63; ++j) acc += ee[j] * wrow[(size_t)j * HID];
        }
        g_c0p[cb][fp][h] = acc;
    }
}

// ============ K_B: finalize stats+c0 (1) | degree count (157) | bucket scatter (313) ============
__global__ void __launch_bounds__(256) kB(const int* __restrict__ ei) {
    int b = blockIdx.x, t = threadIdx.x;
    if (b == 0) {
        float s = 0.f, q = 0.f;
        for (int i = 0; i < SB; ++i) { s += g_stat[i][0][t]; q += g_stat[i][1][t]; }
        float m = s / N_NODES;
        float var = fmaxf(q / N_NODES - m * m, 0.f);
        float sd = sqrtf(var);
        if (sd == 0.f) sd = 1.f;
        g_mean[t] = m; g_rstd[t] = 1.f / sd;
        if (t < HID) {
            float c = 0.f;
            for (int i = 0; i < 64; ++i) c += g_c0p[i][0][t] + g_c0p[i][1][t];
            g_c0[t] = c;
        }
    } else if (b <= SB) {
        int base = ((b - 1) * 256 + t) * 8;
        if (base < E_EDGES) {
            const int4* p = (const int4*)(ei + E_EDGES + base);
            int4 d0 = p[0], d1 = p[1];
            atomicAdd(&g_deg[d0.x], 1); atomicAdd(&g_deg[d0.y], 1);
            atomicAdd(&g_deg[d0.z], 1); atomicAdd(&g_deg[d0.w], 1);
            atomicAdd(&g_deg[d1.x], 1); atomicAdd(&g_deg[d1.y], 1);
            atomicAdd(&g_deg[d1.z], 1); atomicAdd(&g_deg[d1.w], 1);
        }
    } else {
        int base = ((b - SB - 1) * 256 + t) * 4;
        if (base < E_EDGES) {
            int4 s4 = *(const int4*)(ei + base);
            int4 d4 = *(const int4*)(ei + E_EDGES + base);
            int s[4] = {s4.x, s4.y, s4.z, s4.w};
            int d[4] = {d4.x, d4.y, d4.z, d4.w};
            int p[4];
            #pragma unroll
            for (int i = 0; i < 4; ++i) p[i] = atomicAdd(&g_cur[d[i]], 1);
            #pragma unroll
            for (int i = 0; i < 4; ++i)
                if (p[i] < BKT) g_csrc[d[i] * BKT + p[i]] = s[i];
        }
    }
}

// ============ K_C: dinv (block 0) | tf32 gemm1, 128-row tiles, fp16 dinv-scaled epilogue ============
__global__ void __launch_bounds__(256, 2) kC(const float* __restrict__ x,
                                             const float* __restrict__ W1) {
    __shared__ uint32_t sxh[128 * 36];          // 18.4 KB
    __shared__ uint32_t swh[32 * 136];          // 17.4 KB
    int t = threadIdx.x;
    if (blockIdx.x == 0) {
        for (int i = t; i < N_NODES; i += 256)
            g_dinv[i] = rsqrtf((float)g_deg[i]);
        return;
    }
    int r0 = (blockIdx.x - 1) * 128;
    int w = t >> 5, l = t & 31;
    int mw = w & 1, nw = w >> 1;
    int g = l >> 2, tg = l & 3;
    float c[4][4][4];
    #pragma unroll
    for (int i = 0; i < 4; ++i)
        #pragma unroll
        for (int j = 0; j < 4; ++j)
            #pragma unroll
            for (int k = 0; k < 4; ++k) c[i][j][k] = 0.f;

    for (int kc = 0; kc < 8; ++kc) {
        int k0 = kc * 32;
        #pragma unroll
        for (int i = 0; i < 16; ++i) {          // x tile 128x32, standardized -> tf32
            int e = t + i * 256;
            int row = e >> 5, col = e & 31;
            int rr = min(r0 + row, N_NODES - 1);
            int cc = k0 + col;
            float v = (x[(size_t)rr * F_DIM + cc] - g_mean[cc]) * g_rstd[cc];
            sxh[row * 36 + col] = f2tf(v);
        }
        #pragma unroll
        for (int i = 0; i < 16; ++i) {          // W tile 32x128
            int e = t + i * 256;
            int n = e & 127, kk = e >> 7;
            swh[kk * 136 + n] = f2tf(W1[((size_t)(k0 + kk) * 64 + 63) * HID + n]);
        }
        __syncthreads();
        #pragma unroll
        for (int ks = 0; ks < 4; ++ks) {
            int kb = ks * 8;
            uint32_t ah[4][4];
            #pragma unroll
            for (int mt = 0; mt < 4; ++mt) {
                int mr = mw * 64 + mt * 16 + g;
                ah[mt][0] = sxh[mr * 36 + kb + tg];
                ah[mt][1] = sxh[(mr + 8) * 36 + kb + tg];
                ah[mt][2] = sxh[mr * 36 + kb + tg + 4];
                ah[mt][3] = sxh[(mr + 8) * 36 + kb + tg + 4];
            }
            #pragma unroll
            for (int nt = 0; nt < 4; ++nt) {
                int nc = nw * 32 + nt * 8 + g;
                uint32_t b0 = swh[(kb + tg) * 136 + nc];
                uint32_t b1 = swh[(kb + tg + 4) * 136 + nc];
                #pragma unroll
                for (int mt = 0; mt < 4; ++mt)
                    mma8(c[mt][nt], ah[mt][0], ah[mt][1], ah[mt][2], ah[mt][3], b0, b1);
            }
        }
        __syncthreads();
    }
    #pragma unroll
    for (int mt = 0; mt < 4; ++mt) {
        int row0 = r0 + mw * 64 + mt * 16 + g;
        float dv0 = (row0 < N_NODES) ? rsqrtf((float)g_deg[row0]) : 0.f;
        float dv1 = (row0 + 8 < N_NODES) ? rsqrtf((float)g_deg[row0 + 8]) : 0.f;
        #pragma unroll
        for (int nt = 0; nt < 4; ++nt) {
            int col = nw * 32 + nt * 8 + 2 * tg;
            float cc0 = g_c0[col], cc1 = g_c0[col + 1];
            if (row0 < N_NODES)
                g_g1h[(size_t)row0 * 64 + (col >> 1)] =
                    __floats2half2_rn((c[mt][nt][0] + cc0) * dv0, (c[mt][nt][1] + cc1) * dv0);
            if (row0 + 8 < N_NODES)
                g_g1h[(size_t)(row0 + 8) * 64 + (col >> 1)] =
                    __floats2half2_rn((c[mt][nt][2] + cc0) * dv1, (c[mt][nt][3] + cc1) * dv1);
        }
    }
}

// ============ K_E: conv1 aggregate + relu + gemm2, fused (one warp per node) ============
// g1 fp16, pre-scaled -> gather loop = 8B load + 2 cvt + 4 add per edge.
__global__ void __launch_bounds__(256, 6) kE(const float* __restrict__ b1,
                                             const float* __restrict__ W2) {
    __shared__ float sW2[HID * OUTC];           // [h][o], 3.5 KB
    int t = threadIdx.x, w = t >> 5, l = t & 31;
    for (int i = t; i < HID * OUTC; i += 256) sW2[i] = W2[i];
    __syncthreads();

    int n = blockIdx.x * 8 + w;                 // 2500 blocks x 8 warps
    float4 b1v = ((const float4*)b1)[l];

    float dn = g_dinv[n];
    const int* bkt = g_csrc + n * BKT;
    int ne = min(g_deg[n] - 1, BKT);

    int myidx = (l < ne) ? bkt[l] : 0;          // lane-parallel index prefetch

    float4 acc = make_float4(0.f, 0.f, 0.f, 0.f);
    {
        uint2 u = *(const uint2*)(g_g1h + (size_t)n * 64 + 2 * l);  // self (pre-scaled)
        float2 f0 = __half22float2(*(__half2*)&u.x);
        float2 f1 = __half22float2(*(__half2*)&u.y);
        acc.x += f0.x; acc.y += f0.y; acc.z += f1.x; acc.w += f1.y;
    }
    int nel = min(ne, 32);
    #pragma unroll 8
    for (int e = 0; e < nel; ++e) {
        int s = __shfl_sync(0xffffffffu, myidx, e);
        uint2 u = *(const uint2*)(g_g1h + (size_t)s * 64 + 2 * l);
        float2 f0 = __half22float2(*(__half2*)&u.x);
        float2 f1 = __half22float2(*(__half2*)&u.y);
        acc.x += f0.x; acc.y += f0.y; acc.z += f1.x; acc.w += f1.y;
    }
    for (int e = 32; e < ne; ++e) {             // rare tail (deg > 33)
        int s = bkt[e];
        uint2 u = *(const uint2*)(g_g1h + (size_t)s * 64 + 2 * l);
        float2 f0 = __half22float2(*(__half2*)&u.x);
        float2 f1 = __half22float2(*(__half2*)&u.y);
        acc.x += f0.x; acc.y += f0.y; acc.z += f1.x; acc.w += f1.y;
    }

    float h0 = fmaxf(acc.x * dn + b1v.x, 0.f);
    float h1 = fmaxf(acc.y * dn + b1v.y, 0.f);
    float h2 = fmaxf(acc.z * dn + b1v.z, 0.f);
    float h3 = fmaxf(acc.w * dn + b1v.w, 0.f);
    const float* w0 = sW2 + (4 * l + 0) * OUTC;
    const float* w1 = sW2 + (4 * l + 1) * OUTC;
    const float* w2 = sW2 + (4 * l + 2) * OUTC;
    const float* w3 = sW2 + (4 * l + 3) * OUTC;
    float po[7];
    #pragma unroll
    for (int o = 0; o < 7; ++o)
        po[o] = h0 * w0[o] + h1 * w1[o] + h2 * w2[o] + h3 * w3[o];
    #pragma unroll
    for (int o = 0; o < 7; ++o)
        #pragma unroll
        for (int d2 = 16; d2 > 0; d2 >>= 1)
            po[o] += __shfl_xor_sync(0xffffffffu, po[o], d2);
    if (l == 0) {
        float4* gp = (float4*)(g_g2 + n * 8);
        gp[0] = make_float4(po[0] * dn, po[1] * dn, po[2] * dn, po[3] * dn);
        gp[1] = make_float4(po[4] * dn, po[5] * dn, po[6] * dn, 0.f);
    }
}

// ============ K_F: conv2 aggregate + bias + log_softmax (8-lane subgroup prefetch) ============
__global__ void __launch_bounds__(128) kF(const float* __restrict__ b2,
                                          float* __restrict__ out) {
    int t = threadIdx.x;
    int l = t & 31;
    int n = blockIdx.x * 16 + (t >> 3);
    int o = t & 7;
    unsigned gm = 0xFFu << (l & 24);            // this 8-lane group's mask
    float dn = g_dinv[n];
    const int* bkt = g_csrc + n * BKT;
    int ne = min(g_deg[n] - 1, BKT);

    int i0 = (o < ne)      ? bkt[o]      : 0;
    int i1 = (8 + o < ne)  ? bkt[8 + o]  : 0;
    int i2 = (16 + o < ne) ? bkt[16 + o] : 0;
    int i3 = (24 + o < ne) ? bkt[24 + o] : 0;

    float acc = g_g2[n * 8 + o];                // self (pre-scaled)
    int nel = min(ne, 32);
    int full = nel >> 3, rem = nel & 7;
    int pidx[4] = {i0, i1, i2, i3};
    #pragma unroll
    for (int p = 0; p < 4; ++p) {
        if (p < full) {
            #pragma unroll
            for (int k = 0; k < 8; ++k) {
                int s = __shfl_sync(gm, pidx[p], k, 8);
                acc += g_g2[s * 8 + o];
            }
        } else if (p == full) {
            for (int k = 0; k < rem; ++k) {
                int s = __shfl_sync(gm, pidx[p], k, 8);
                acc += g_g2[s * 8 + o];
            }
        }
    }
    for (int e = 32; e < ne; ++e)               // rare tail
        acc += g_g2[bkt[e] * 8 + o];

    float v = (o < OUTC) ? (acc * dn + b2[o]) : -3.0e38f;
    float m = v;
    #pragma unroll
    for (int d = 1; d < 8; d <<= 1) m = fmaxf(m, __shfl_xor_sync(0xffffffffu, m, d));
    float ex = (o < OUTC) ? expf(v - m) : 0.f;
    float s2 = ex;
    #pragma unroll
    for (int d = 1; d < 8; d <<= 1) s2 += __shfl_xor_sync(0xffffffffu, s2, d);
    if (o < OUTC) out[n * OUTC + o] = v - m - logf(s2);
}

// ---------------- launcher ----------------
extern "C" void kernel_launch(void* const* d_in, const int* in_sizes, int n_in,
                              void* d_out, int out_size) {
    const float* x   = (const float*)d_in[0];
    const float* emb = (const float*)d_in[1];
    const float* W1  = (const float*)d_in[2];
    const float* b1  = (const float*)d_in[3];
    const float* W2  = (const float*)d_in[4];
    const float* b2  = (const float*)d_in[5];
    const int*   ei  = (const int*)d_in[6];
    float* out = (float*)d_out;

    kA<<<300, 256>>>(x, emb, W1);        // stats partials | deg/cur init | c0 partials
    kB<<<1 + SB + 313, 256>>>(ei);       // stats+c0 finalize | count | bucket scatter
    kC<<<158, 256>>>(x, W1);             // dinv | tf32 gemm1 (128-row tiles, fp16 out)
    kE<<<2500, 256>>>(b1, W2);           // agg1 + relu + gemm2 fused (warp/node)
    kF<<<1250, 128>>>(b2, out);          // agg2 + log_softmax
}